// round 13
// baseline (speedup 1.0000x reference)
#include <cuda_runtime.h>
#include <cstdint>

// Problem constants
#define Bdim 8
#define Tdim 64
#define Ndim 128
#define Ddim 64
#define LAGn 8
#define ROWS (Bdim*Tdim*Ndim)   // 65536

typedef unsigned long long u64;

// Scratch (no cudaMalloc allowed)
// g_Q: [bt][f=64][n=128]  (TRANSPOSED)
// g_K: [bt][f=64][m=128]  (TRANSPOSED, pre-scaled by 0.125*log2(e))
// g_V: [bt][m=128][d=64]  (natural)
__device__ float g_Q[ROWS*Ddim];
__device__ float g_K[ROWS*Ddim];
__device__ float g_V[ROWS*Ddim];

// Packed fp32x2 helpers
#define PKDUP(dst, f32v) asm("mov.b64 %0, {%1, %1};" : "=l"(dst) : "f"(f32v))
#define PK2(dst, lo, hi) asm("mov.b64 %0, {%1, %2};" : "=l"(dst) : "f"(lo), "f"(hi))
#define FMA2(acc, a, b)  asm("fma.rn.f32x2 %0, %1, %2, %0;" : "+l"(acc) : "l"(a), "l"(b))
#define MUL2(acc, a)     asm("mul.rn.f32x2 %0, %0, %1;" : "+l"(acc) : "l"(a))
#define ADD2(acc, a)     asm("add.rn.f32x2 %0, %0, %1;" : "+l"(acc) : "l"(a))
#define UNPK(lo, hi, v)  asm("mov.b64 {%0, %1}, %2;" : "=f"(lo), "=f"(hi) : "l"(v))
#define EX2(y, x)        asm("ex2.approx.f32 %0, %1;" : "=f"(y) : "f"(x))

// cp.async helpers
#define CPA16(d, s)   asm volatile("cp.async.cg.shared.global [%0], [%1], 16;" :: "r"(d), "l"(s) : "memory")
#define CPA_COMMIT()  asm volatile("cp.async.commit_group;" ::: "memory")
#define CPA_WAIT0()   asm volatile("cp.async.wait_group 0;" ::: "memory")
#define CPA_WAIT1()   asm volatile("cp.async.wait_group 1;" ::: "memory")

__device__ __forceinline__ uint32_t smem_u32(const void* p) {
    uint32_t a;
    asm("{ .reg .u64 t; cvta.to.shared.u64 t, %1; cvt.u32.u64 %0, t; }" : "=r"(a) : "l"(p));
    return a;
}

// ---------------------------------------------------------------------------
// Kernel 1: QKV projection, row-pair packed (R10/R11 version). grid = (512, 3).
// ---------------------------------------------------------------------------
__global__ __launch_bounds__(256) void qkv_kernel(
    const float* __restrict__ X,
    const float* __restrict__ Wq, const float* __restrict__ bq,
    const float* __restrict__ Wk, const float* __restrict__ bk,
    const float* __restrict__ Wv, const float* __restrict__ bv)
{
    __shared__ float XsT[64*128];   // 32 KB
    __shared__ float Ws [64*64];    // 16 KB
    __shared__ float bs [64];

    const float* W; const float* bias; float scale;
    if (blockIdx.y == 0)      { W = Wq; bias = bq; scale = 1.0f; }
    else if (blockIdx.y == 1) { W = Wk; bias = bk; scale = 0.125f * 1.4426950408889634f; }
    else                      { W = Wv; bias = bv; scale = 1.0f; }

    const int bt  = blockIdx.x;
    const int r0  = bt * 128;
    const int tid = threadIdx.x;

    {
        const float4* Xg = reinterpret_cast<const float4*>(X + (size_t)r0 * 64);
        const float4* Wg = reinterpret_cast<const float4*>(W);
        #pragma unroll
        for (int q = 0; q < 4; ++q) {
            int idx4 = tid + q * 256;
            reinterpret_cast<float4*>(Ws)[idx4] = Wg[idx4];
        }
        #pragma unroll
        for (int b = 0; b < 2; ++b) {
            int blk = tid + b * 256;
            int r4  = blk >> 4;
            int f4  = blk & 15;
            float4 v0 = Xg[(r4*4+0)*16 + f4];
            float4 v1 = Xg[(r4*4+1)*16 + f4];
            float4 v2 = Xg[(r4*4+2)*16 + f4];
            float4 v3 = Xg[(r4*4+3)*16 + f4];
            int rb = (r4 ^ (f4 & 7)) << 2;
            *reinterpret_cast<float4*>(&XsT[(f4*4+0)*128 + rb]) = make_float4(v0.x, v1.x, v2.x, v3.x);
            *reinterpret_cast<float4*>(&XsT[(f4*4+1)*128 + rb]) = make_float4(v0.y, v1.y, v2.y, v3.y);
            *reinterpret_cast<float4*>(&XsT[(f4*4+2)*128 + rb]) = make_float4(v0.z, v1.z, v2.z, v3.z);
            *reinterpret_cast<float4*>(&XsT[(f4*4+3)*128 + rb]) = make_float4(v0.w, v1.w, v2.w, v3.w);
        }
        if (tid < 64) bs[tid] = bias[tid];
    }
    __syncthreads();

    const int tx = tid & 15;
    const int ty = tid >> 4;
    const int rbase = ty << 3;

    u64 acc[4][4];
    #pragma unroll
    for (int i = 0; i < 4; ++i)
        #pragma unroll
        for (int d = 0; d < 4; ++d) acc[i][d] = 0ull;

    #pragma unroll 4
    for (int k = 0; k < 64; ++k) {
        int sw = (k >> 2) & 7;
        ulonglong2 a01 = *reinterpret_cast<const ulonglong2*>(&XsT[k*128 + (((2*ty    ) ^ sw) << 2)]);
        ulonglong2 a23 = *reinterpret_cast<const ulonglong2*>(&XsT[k*128 + (((2*ty + 1) ^ sw) << 2)]);
        float4 wv = *reinterpret_cast<const float4*>(&Ws[k*64 + (tx<<2)]);
        float ws4[4] = {wv.x, wv.y, wv.z, wv.w};
        #pragma unroll
        for (int d = 0; d < 4; ++d) {
            u64 wd; PKDUP(wd, ws4[d]);
            FMA2(acc[0][d], a01.x, wd);
            FMA2(acc[1][d], a01.y, wd);
            FMA2(acc[2][d], a23.x, wd);
            FMA2(acc[3][d], a23.y, wd);
        }
    }

    float o[8][4];
    #pragma unroll
    for (int i = 0; i < 4; ++i)
        #pragma unroll
        for (int d = 0; d < 4; ++d)
            UNPK(o[2*i][d], o[2*i+1][d], acc[i][d]);
    #pragma unroll
    for (int i = 0; i < 8; ++i)
        #pragma unroll
        for (int j = 0; j < 4; ++j)
            o[i][j] = fmaxf(o[i][j] + bs[(tx<<2)+j], 0.0f) * scale;

    if (blockIdx.y == 2) {
        #pragma unroll
        for (int i = 0; i < 8; ++i) {
            int r = r0 + rbase + i;
            *reinterpret_cast<float4*>(&g_V[(size_t)r*64 + (tx<<2)]) =
                make_float4(o[i][0], o[i][1], o[i][2], o[i][3]);
        }
    } else {
        float* outp = blockIdx.y ? g_K : g_Q;
        #pragma unroll
        for (int j = 0; j < 4; ++j) {
            int d = (tx<<2) + j;
            float* base = &outp[(size_t)bt*8192 + d*128 + rbase];
            *reinterpret_cast<float4*>(base)     = make_float4(o[0][j], o[1][j], o[2][j], o[3][j]);
            *reinterpret_cast<float4*>(base + 4) = make_float4(o[4][j], o[5][j], o[6][j], o[7][j]);
        }
    }
}

// ---------------------------------------------------------------------------
// Kernel 2: software-pipelined fused lag-attention + output projection.
// grid = B*T*2 (one per (bt, half)), 128 threads, 56 KB smem -> 4 CTAs/SM.
// 32-key chunks; per chunk: phase E (exp->P) then phase C which INTERLEAVES
// GEMM2(ic) with GEMM1(ic+1) (independent accumulators). K,V double-buffered
// (chunk ic in buffer ic&1); single P buffer. 2 barriers + 1 wait per chunk.
// K chunk = 64f x 32m = 8KB = 512 CPA16 (4 loops x 128 thr). Same for V.
// ---------------------------------------------------------------------------
#define SMF_Q  0
#define SMF_K0 4096
#define SMF_K1 6144
#define SMF_V0 8192
#define SMF_V1 10240
#define SMF_P  12288
#define SMEM_ATTN (14336*4)   // 56 KB -> 4 CTAs/SM

__global__ __launch_bounds__(128, 4) void attn_kernel(
    const float* __restrict__ Wo, const float* __restrict__ bo,
    float* __restrict__ out)
{
    extern __shared__ float sm[];
    float* Qst = sm + SMF_Q;     // [64 f][64 r]   16 KB
    float* Pp  = sm + SMF_P;     // [32 m][32 rp u64] 8 KB
    float* aggT = sm + SMF_K0;   // alias after loop: [64 c][32 rp u64] 16 KB (K0+K1)
    float* Wos  = sm + SMF_V0;   // alias after loop: [64 c][64 d] 16 KB (V0+V1)

    const int gid  = blockIdx.x;
    const int half = gid & 1;
    const int bt   = gid >> 1;
    const int t    = bt & (Tdim - 1);
    const int tid  = threadIdx.x;
    const int tx   = tid & 15;
    const int ty   = tid >> 4;          // 0..7
    const int rbase = ty << 3;

    const uint32_t sK0 = smem_u32(sm + SMF_K0);
    const uint32_t sK1 = smem_u32(sm + SMF_K1);
    const uint32_t sV0 = smem_u32(sm + SMF_V0);
    const uint32_t sV1 = smem_u32(sm + SMF_V1);

    const int nvalid  = (t + 1 < LAGn) ? (t + 1) : LAGn;
    const int nchunks = nvalid * 4;     // 32-key chunks

    // Prologue: G1 = {Q, K0}; G2 = {K1, V0}.
    {
        const float* Qg = g_Q + (size_t)bt*8192 + half*64;
        const float* Kg = g_K + (size_t)bt*8192;
        const float* Vg = g_V + (size_t)bt*8192;
        const uint32_t sQ = smem_u32(Qst);
        #pragma unroll
        for (int q = 0; q < 8; ++q) {
            int idx4 = tid + q * 128;        // 0..1023
            int f = idx4 >> 4, c = idx4 & 15;
            CPA16(sQ + (uint32_t)idx4*16, Qg + f*128 + c*4);
        }
        #pragma unroll
        for (int q = 0; q < 4; ++q) {        // K0: cols 0..31 (8 KB)
            int idx4 = tid + q * 128;        // 0..511
            int f = idx4 >> 3, u = idx4 & 7;
            CPA16(sK0 + (uint32_t)idx4*16, Kg + f*128 + u*4);
        }
        CPA_COMMIT();   // G1
        #pragma unroll
        for (int q = 0; q < 4; ++q) {        // K1: cols 32..63 ; V0: rows 0..31
            int idx4 = tid + q * 128;        // 0..511
            int f = idx4 >> 3, u = idx4 & 7;
            CPA16(sK1 + (uint32_t)idx4*16, Kg + f*128 + 32 + u*4);
            CPA16(sV0 + (uint32_t)idx4*16, Vg + idx4*4);
        }
        CPA_COMMIT();   // G2
    }

    u64 dpack[4];   // packed denominators, row pairs rp = 4*ty+i
    u64 Op[4][4];   // [rp][d]
    u64 sa[4][2];   // [rp][m half], m = 2*tx+mm
    #pragma unroll
    for (int i = 0; i < 4; ++i) {
        dpack[i] = 0ull;
        sa[i][0] = 0ull; sa[i][1] = 0ull;
        #pragma unroll
        for (int d = 0; d < 4; ++d) Op[i][d] = 0ull;
    }

    // Hoisted P-store offsets.
    int poff[4];
    #pragma unroll
    for (int i = 0; i < 4; ++i) {
        int rp = (ty<<2) + i;
        poff[i] = (((rp>>1) ^ (tx&7)) << 2) + ((rp & 1) << 1);
    }

    CPA_WAIT1();        // G1 = {Q, K0} ready
    __syncthreads();

    // Prologue GEMM1(0) on K buffer 0.
    {
        const float* Kc = sm + SMF_K0;
        #pragma unroll 8
        for (int k = 0; k < 64; ++k) {
            ulonglong2 a01 = *reinterpret_cast<const ulonglong2*>(&Qst[k*64 + rbase]);
            ulonglong2 a23 = *reinterpret_cast<const ulonglong2*>(&Qst[k*64 + rbase + 4]);
            float2 bv = *reinterpret_cast<const float2*>(&Kc[k*32 + (tx<<1)]);
            u64 b0; PKDUP(b0, bv.x);
            u64 b1; PKDUP(b1, bv.y);
            FMA2(sa[0][0], a01.x, b0);
            FMA2(sa[1][0], a01.y, b0);
            FMA2(sa[2][0], a23.x, b0);
            FMA2(sa[3][0], a23.y, b0);
            FMA2(sa[0][1], a01.x, b1);
            FMA2(sa[1][1], a01.y, b1);
            FMA2(sa[2][1], a23.x, b1);
            FMA2(sa[3][1], a23.y, b1);
        }
    }

    for (int ic = 0; ic < nchunks; ++ic) {
        // ---- phase E: exp(S(ic)) -> P, denom ----
        #pragma unroll
        for (int i = 0; i < 4; ++i) {
            #pragma unroll
            for (int mm = 0; mm < 2; ++mm) {
                float lo, hi;
                UNPK(lo, hi, sa[i][mm]);
                float elo, ehi;
                EX2(elo, lo); EX2(ehi, hi);
                u64 pe; PK2(pe, elo, ehi);
                ADD2(dpack[i], pe);
                *reinterpret_cast<u64*>(&Pp[((tx<<1)+mm)*64 + poff[i]]) = pe;
            }
        }

        CPA_WAIT0();       // {K(ic+1), V(ic)} (group from C(ic-1) / prologue) done
        __syncthreads();   // P published; prev GEMM2's P/V reads done

        // Prefetch {K(ic+2), V(ic+1)} (overlaps phase C). One group per chunk.
        {
            if (ic + 2 < nchunks) {
                const int jc = ic + 2;
                const float* Kg = g_K + (size_t)(bt - (jc>>2)) * 8192 + ((jc&3) << 5);
                const uint32_t sKd = (jc & 1) ? sK1 : sK0;
                #pragma unroll
                for (int q = 0; q < 4; ++q) {
                    int idx4 = tid + q * 128;   // 0..511
                    int f = idx4 >> 3, u = idx4 & 7;
                    CPA16(sKd + (uint32_t)idx4*16, Kg + f*128 + u*4);
                }
            }
            if (ic + 1 < nchunks) {
                const int jc = ic + 1;
                const float* Vg = g_V + ((size_t)(bt - (jc>>2)) * 128 + ((jc&3) << 5)) * 64;
                const uint32_t sVd = (jc & 1) ? sV1 : sV0;
                #pragma unroll
                for (int q = 0; q < 4; ++q) {
                    int idx4 = tid + q * 128;   // 0..511
                    CPA16(sVd + (uint32_t)idx4*16, Vg + idx4*4);
                }
            }
            CPA_COMMIT();
        }

        const float* Vc = sm + ((ic & 1) ? SMF_V1 : SMF_V0);

        if (ic + 1 < nchunks) {
            // ---- phase C: GEMM2(ic) + GEMM1(ic+1) interleaved ----
            const float* Kn = sm + (((ic + 1) & 1) ? SMF_K1 : SMF_K0);
            #pragma unroll
            for (int i = 0; i < 4; ++i) { sa[i][0] = 0ull; sa[i][1] = 0ull; }

            #pragma unroll 4
            for (int j = 0; j < 32; ++j) {
                // GEMM1(ic+1): k = 2j, 2j+1
                #pragma unroll
                for (int kk = 0; kk < 2; ++kk) {
                    const int k = 2*j + kk;
                    ulonglong2 a01 = *reinterpret_cast<const ulonglong2*>(&Qst[k*64 + rbase]);
                    ulonglong2 a23 = *reinterpret_cast<const ulonglong2*>(&Qst[k*64 + rbase + 4]);
                    float2 bv = *reinterpret_cast<const float2*>(&Kn[k*32 + (tx<<1)]);
                    u64 b0; PKDUP(b0, bv.x);
                    u64 b1; PKDUP(b1, bv.y);
                    FMA2(sa[0][0], a01.x, b0);
                    FMA2(sa[1][0], a01.y, b0);
                    FMA2(sa[2][0], a23.x, b0);
                    FMA2(sa[3][0], a23.y, b0);
                    FMA2(sa[0][1], a01.x, b1);
                    FMA2(sa[1][1], a01.y, b1);
                    FMA2(sa[2][1], a23.x, b1);
                    FMA2(sa[3][1], a23.y, b1);
                }
                // GEMM2(ic): m = j
                {
                    const int x = (j >> 1) & 7;
                    ulonglong2 p01 = *reinterpret_cast<const ulonglong2*>(
                        &Pp[j*64 + ((((ty<<1)    ) ^ x) << 2)]);
                    ulonglong2 p23 = *reinterpret_cast<const ulonglong2*>(
                        &Pp[j*64 + ((((ty<<1) | 1) ^ x) << 2)]);
                    float4 vv = *reinterpret_cast<const float4*>(&Vc[j*64 + (tx<<2)]);
                    float vs4[4] = {vv.x, vv.y, vv.z, vv.w};
                    #pragma unroll
                    for (int d = 0; d < 4; ++d) {
                        u64 vd; PKDUP(vd, vs4[d]);
                        FMA2(Op[0][d], p01.x, vd);
                        FMA2(Op[1][d], p01.y, vd);
                        FMA2(Op[2][d], p23.x, vd);
                        FMA2(Op[3][d], p23.y, vd);
                    }
                }
            }
        } else {
            // ---- last chunk: GEMM2 only ----
            #pragma unroll 4
            for (int j = 0; j < 32; ++j) {
                const int x = (j >> 1) & 7;
                ulonglong2 p01 = *reinterpret_cast<const ulonglong2*>(
                    &Pp[j*64 + ((((ty<<1)    ) ^ x) << 2)]);
                ulonglong2 p23 = *reinterpret_cast<const ulonglong2*>(
                    &Pp[j*64 + ((((ty<<1) | 1) ^ x) << 2)]);
                float4 vv = *reinterpret_cast<const float4*>(&Vc[j*64 + (tx<<2)]);
                float vs4[4] = {vv.x, vv.y, vv.z, vv.w};
                #pragma unroll
                for (int d = 0; d < 4; ++d) {
                    u64 vd; PKDUP(vd, vs4[d]);
                    FMA2(Op[0][d], p01.x, vd);
                    FMA2(Op[1][d], p01.y, vd);
                    FMA2(Op[2][d], p23.x, vd);
                    FMA2(Op[3][d], p23.y, vd);
                }
            }
        }
        __syncthreads();   // P free for next E write; V(ic) reads done
    }

    // ---- denominators: reduce over 16 tx lanes, packed inverses ----
    const float padadd = (float)(LAGn - nvalid) * 128.0f;   // 2^0 per padded key
    u64 invp[4];
    #pragma unroll
    for (int i = 0; i < 4; ++i) {
        float d0, d1;
        UNPK(d0, d1, dpack[i]);
        d0 += __shfl_xor_sync(0xffffffffu, d0, 1);
        d1 += __shfl_xor_sync(0xffffffffu, d1, 1);
        d0 += __shfl_xor_sync(0xffffffffu, d0, 2);
        d1 += __shfl_xor_sync(0xffffffffu, d1, 2);
        d0 += __shfl_xor_sync(0xffffffffu, d0, 4);
        d1 += __shfl_xor_sync(0xffffffffu, d1, 4);
        d0 += __shfl_xor_sync(0xffffffffu, d0, 8);
        d1 += __shfl_xor_sync(0xffffffffu, d1, 8);
        PK2(invp[i], 1.0f / (d0 + padadd), 1.0f / (d1 + padadd));
    }

    CPA_WAIT0();
    __syncthreads();   // drain; all smem reusable

    // agg (normalized, row-pair u64) -> aggT; Wo[0:64] -> Wos.
    {
        const int key2 = (tx & 7) << 1;
        #pragma unroll
        for (int i = 0; i < 4; ++i) {
            const int rp = (ty<<2) + i;
            #pragma unroll
            for (int dd = 0; dd < 4; ++dd) {
                MUL2(Op[i][dd], invp[i]);
                const int c = (tx<<2) + dd;
                *reinterpret_cast<u64*>(&aggT[c*64 + ((rp ^ key2) << 1)]) = Op[i][dd];
            }
        }
        const float4* Wg = reinterpret_cast<const float4*>(Wo);
        #pragma unroll
        for (int q = 0; q < 8; ++q) {
            int idx4 = tid + q * 128;   // 0..1023 -> Wo rows 0..63
            reinterpret_cast<float4*>(Wos)[idx4] = Wg[idx4];
        }
    }
    __syncthreads();

    // ---- epilogue pass 1: ec = Q @ Wo[0:64] ----
    u64 ec[4][4];
    #pragma unroll
    for (int i = 0; i < 4; ++i)
        #pragma unroll
        for (int d = 0; d < 4; ++d) ec[i][d] = 0ull;

    #pragma unroll 4
    for (int c = 0; c < 64; ++c) {
        ulonglong2 a01 = *reinterpret_cast<const ulonglong2*>(&Qst[c*64 + rbase]);
        ulonglong2 a23 = *reinterpret_cast<const ulonglong2*>(&Qst[c*64 + rbase + 4]);
        float4 wv = *reinterpret_cast<const float4*>(&Wos[c*64 + (tx<<2)]);
        float ws4[4] = {wv.x, wv.y, wv.z, wv.w};
        #pragma unroll
        for (int d = 0; d < 4; ++d) {
            u64 wd; PKDUP(wd, ws4[d]);
            FMA2(ec[0][d], a01.x, wd);
            FMA2(ec[1][d], a01.y, wd);
            FMA2(ec[2][d], a23.x, wd);
            FMA2(ec[3][d], a23.y, wd);
        }
    }
    __syncthreads();   // Wos reads done

    // Load Wo[64:128]
    {
        const float4* Wg = reinterpret_cast<const float4*>(Wo) + 1024;
        #pragma unroll
        for (int q = 0; q < 8; ++q) {
            int idx4 = tid + q * 128;
            reinterpret_cast<float4*>(Wos)[idx4] = Wg[idx4];
        }
    }
    __syncthreads();

    // ---- epilogue pass 2: ec += agg @ Wo[64:128] ----
    #pragma unroll 4
    for (int c = 0; c < 64; ++c) {
        const int y = ((c >> 2) & 7) << 1;
        ulonglong2 a01 = *reinterpret_cast<const ulonglong2*>(
            &aggT[c*64 + ((((ty<<2)    ) ^ y) << 1)]);
        ulonglong2 a23 = *reinterpret_cast<const ulonglong2*>(
            &aggT[c*64 + ((((ty<<2) + 2) ^ y) << 1)]);
        float4 wv = *reinterpret_cast<const float4*>(&Wos[c*64 + (tx<<2)]);
        float ws4[4] = {wv.x, wv.y, wv.z, wv.w};
        #pragma unroll
        for (int d = 0; d < 4; ++d) {
            u64 wd; PKDUP(wd, ws4[d]);
            FMA2(ec[0][d], a01.x, wd);
            FMA2(ec[1][d], a01.y, wd);
            FMA2(ec[2][d], a23.x, wd);
            FMA2(ec[3][d], a23.y, wd);
        }
    }

    float bo4[4];
    #pragma unroll
    for (int j = 0; j < 4; ++j) bo4[j] = bo[(tx<<2) + j];

    #pragma unroll
    for (int i = 0; i < 4; ++i) {
        float e0[4], e1[4];
        #pragma unroll
        for (int d = 0; d < 4; ++d) UNPK(e0[d], e1[d], ec[i][d]);
        size_t row0 = (size_t)bt * Ndim + half*64 + rbase + 2*i;
        float4 o0, o1;
        o0.x = fmaxf(e0[0] + bo4[0], 0.0f);
        o0.y = fmaxf(e0[1] + bo4[1], 0.0f);
        o0.z = fmaxf(e0[2] + bo4[2], 0.0f);
        o0.w = fmaxf(e0[3] + bo4[3], 0.0f);
        o1.x = fmaxf(e1[0] + bo4[0], 0.0f);
        o1.y = fmaxf(e1[1] + bo4[1], 0.0f);
        o1.z = fmaxf(e1[2] + bo4[2], 0.0f);
        o1.w = fmaxf(e1[3] + bo4[3], 0.0f);
        *reinterpret_cast<float4*>(&out[row0 * Ddim + (tx<<2)])       = o0;
        *reinterpret_cast<float4*>(&out[(row0 + 1) * Ddim + (tx<<2)]) = o1;
    }
}

// ---------------------------------------------------------------------------
extern "C" void kernel_launch(void* const* d_in, const int* in_sizes, int n_in,
                              void* d_out, int out_size)
{
    const float* X  = (const float*)d_in[0];
    const float* Wq = (const float*)d_in[1];
    const float* bq = (const float*)d_in[2];
    const float* Wk = (const float*)d_in[3];
    const float* bk = (const float*)d_in[4];
    const float* Wv = (const float*)d_in[5];
    const float* bv = (const float*)d_in[6];
    const float* Wo = (const float*)d_in[7];
    const float* bo = (const float*)d_in[8];
    float* out = (float*)d_out;

    cudaFuncSetAttribute(attn_kernel,
                         cudaFuncAttributeMaxDynamicSharedMemorySize, SMEM_ATTN);

    qkv_kernel<<<dim3(Bdim*Tdim, 3, 1), 256>>>(X, Wq, bq, Wk, bk, Wv, bv);
    attn_kernel<<<Bdim*Tdim*2, 128, SMEM_ATTN>>>(Wo, bo, out);
}

// round 14
// speedup vs baseline: 2.4300x; 2.4300x over previous
#include <cuda_runtime.h>
#include <cstdint>

// Problem constants
#define Bdim 8
#define Tdim 64
#define Ndim 128
#define Ddim 64
#define LAGn 8
#define ROWS (Bdim*Tdim*Ndim)   // 65536

typedef unsigned long long u64;

// Scratch (no cudaMalloc allowed)
// g_Q : natural [bt*128 + n][f], tf32-rounded                  (A-frags GEMM1/epilogue)
// g_K : fragment-packed per bt, scaled 0.125*log2e, tf32       (B-frags GEMM1)
//       K[key][f] -> ((key>>3)*8+(f>>3))*64 + ((key&7)*4+(f&3))*2 + ((f>>2)&1)
// g_V : fragment-packed per bt, tf32                            (B-frags GEMM2)
//       V[key][d] -> ((key>>3)*8+(d>>3))*64 + ((d&7)*4+(key&3))*2 + ((key>>2)&1)
// g_WoP: fragment-packed Wo (128x64), tf32                      (B-frags epilogue)
__device__ float g_Q[ROWS*Ddim];
__device__ float g_K[ROWS*Ddim];
__device__ float g_V[ROWS*Ddim];
__device__ float g_WoP[128*64];

// Packed fp32x2 helpers (qkv GEMM)
#define PKDUP(dst, f32v) asm("mov.b64 %0, {%1, %1};" : "=l"(dst) : "f"(f32v))
#define FMA2(acc, a, b)  asm("fma.rn.f32x2 %0, %1, %2, %0;" : "+l"(acc) : "l"(a), "l"(b))
#define UNPK(lo, hi, v)  asm("mov.b64 {%0, %1}, %2;" : "=f"(lo), "=f"(hi) : "l"(v))
#define EX2(y, x)        asm("ex2.approx.f32 %0, %1;" : "=f"(y) : "f"(x))

// cp.async helpers
#define CPA16(d, s)   asm volatile("cp.async.cg.shared.global [%0], [%1], 16;" :: "r"(d), "l"(s) : "memory")
#define CPA_COMMIT()  asm volatile("cp.async.commit_group;" ::: "memory")
#define CPA_WAIT0()   asm volatile("cp.async.wait_group 0;" ::: "memory")
#define CPA_WAIT1()   asm volatile("cp.async.wait_group 1;" ::: "memory")

__device__ __forceinline__ uint32_t smem_u32(const void* p) {
    uint32_t a;
    asm("{ .reg .u64 t; cvta.to.shared.u64 t, %1; cvt.u32.u64 %0, t; }" : "=r"(a) : "l"(p));
    return a;
}
__device__ __forceinline__ uint32_t tf32r(float f) {
    uint32_t u;
    asm("cvt.rna.tf32.f32 %0, %1;" : "=r"(u) : "f"(f));
    return u;
}

// tf32 tensor-core mma (classic mma.sync -> HMMA on sm_103; NOT 103a-gated)
#define MMA(d, a, b0, b1) \
    asm volatile("mma.sync.aligned.m16n8k8.row.col.f32.tf32.tf32.f32 " \
        "{%0,%1,%2,%3}, {%4,%5,%6,%7}, {%8,%9}, {%0,%1,%2,%3};" \
        : "+f"((d)[0]), "+f"((d)[1]), "+f"((d)[2]), "+f"((d)[3]) \
        : "r"((a)[0]), "r"((a)[1]), "r"((a)[2]), "r"((a)[3]), "r"(b0), "r"(b1))

// C-fragment (m16n8 f32) -> A-fragment (m16k8 tf32) permute via shuffles.
// C: c0=(g,2t) c1=(g,2t+1) c2=(g+8,2t) c3=(g+8,2t+1); A: a0=(g,t) a1=(g+8,t) a2=(g,t+4) a3=(g+8,t+4)
__device__ __forceinline__ void c2a(const float* c, uint32_t* a, int src0, int src1, int odd) {
    float e0 = __shfl_sync(0xffffffffu, c[0], src0);
    float e1 = __shfl_sync(0xffffffffu, c[1], src0);
    float f0 = __shfl_sync(0xffffffffu, c[0], src1);
    float f1 = __shfl_sync(0xffffffffu, c[1], src1);
    float g0 = __shfl_sync(0xffffffffu, c[2], src0);
    float g1 = __shfl_sync(0xffffffffu, c[3], src0);
    float h0 = __shfl_sync(0xffffffffu, c[2], src1);
    float h1 = __shfl_sync(0xffffffffu, c[3], src1);
    a[0] = tf32r(odd ? e1 : e0);
    a[2] = tf32r(odd ? f1 : f0);
    a[1] = tf32r(odd ? g1 : g0);
    a[3] = tf32r(odd ? h1 : h0);
}

// ---------------------------------------------------------------------------
// Kernel 0: pack Wo into B-fragment layout (tf32). 1 CTA x 128 threads.
// ---------------------------------------------------------------------------
__global__ void pack_wo_kernel(const float* __restrict__ Wo) {
    int tid = threadIdx.x;
    #pragma unroll 4
    for (int q = 0; q < 64; ++q) {
        int gidx = tid + q * 128;            // 0..8191
        int c = gidx >> 6, d = gidx & 63;
        int fidx = ((c>>3)*8 + (d>>3))*64 + ((d&7)*4 + (c&3))*2 + ((c>>2)&1);
        g_WoP[fidx] = __uint_as_float(tf32r(Wo[gidx]));
    }
}

// ---------------------------------------------------------------------------
// Kernel 1: QKV projection (R13 compute), new stores: Q natural tf32,
// K/V fragment-packed tf32 (scattered STG.32). grid = (512, 3), 256 thr.
// ---------------------------------------------------------------------------
__global__ __launch_bounds__(256) void qkv_kernel(
    const float* __restrict__ X,
    const float* __restrict__ Wq, const float* __restrict__ bq,
    const float* __restrict__ Wk, const float* __restrict__ bk,
    const float* __restrict__ Wv, const float* __restrict__ bv)
{
    __shared__ float XsT[64*128];
    __shared__ float Ws [64*64];
    __shared__ float bs [64];

    const float* W; const float* bias; float scale;
    if (blockIdx.y == 0)      { W = Wq; bias = bq; scale = 1.0f; }
    else if (blockIdx.y == 1) { W = Wk; bias = bk; scale = 0.125f * 1.4426950408889634f; }
    else                      { W = Wv; bias = bv; scale = 1.0f; }

    const int bt  = blockIdx.x;
    const int r0  = bt * 128;
    const int tid = threadIdx.x;

    {
        const float4* Xg = reinterpret_cast<const float4*>(X + (size_t)r0 * 64);
        const float4* Wg = reinterpret_cast<const float4*>(W);
        #pragma unroll
        for (int q = 0; q < 4; ++q) {
            int idx4 = tid + q * 256;
            reinterpret_cast<float4*>(Ws)[idx4] = Wg[idx4];
        }
        #pragma unroll
        for (int b = 0; b < 2; ++b) {
            int blk = tid + b * 256;
            int r4  = blk >> 4;
            int f4  = blk & 15;
            float4 v0 = Xg[(r4*4+0)*16 + f4];
            float4 v1 = Xg[(r4*4+1)*16 + f4];
            float4 v2 = Xg[(r4*4+2)*16 + f4];
            float4 v3 = Xg[(r4*4+3)*16 + f4];
            int rb = (r4 ^ (f4 & 7)) << 2;
            *reinterpret_cast<float4*>(&XsT[(f4*4+0)*128 + rb]) = make_float4(v0.x, v1.x, v2.x, v3.x);
            *reinterpret_cast<float4*>(&XsT[(f4*4+1)*128 + rb]) = make_float4(v0.y, v1.y, v2.y, v3.y);
            *reinterpret_cast<float4*>(&XsT[(f4*4+2)*128 + rb]) = make_float4(v0.z, v1.z, v2.z, v3.z);
            *reinterpret_cast<float4*>(&XsT[(f4*4+3)*128 + rb]) = make_float4(v0.w, v1.w, v2.w, v3.w);
        }
        if (tid < 64) bs[tid] = bias[tid];
    }
    __syncthreads();

    const int tx = tid & 15;
    const int ty = tid >> 4;
    const int rbase = ty << 3;

    u64 acc[4][4];
    #pragma unroll
    for (int i = 0; i < 4; ++i)
        #pragma unroll
        for (int d = 0; d < 4; ++d) acc[i][d] = 0ull;

    #pragma unroll 4
    for (int k = 0; k < 64; ++k) {
        int sw = (k >> 2) & 7;
        ulonglong2 a01 = *reinterpret_cast<const ulonglong2*>(&XsT[k*128 + (((2*ty    ) ^ sw) << 2)]);
        ulonglong2 a23 = *reinterpret_cast<const ulonglong2*>(&XsT[k*128 + (((2*ty + 1) ^ sw) << 2)]);
        float4 wv = *reinterpret_cast<const float4*>(&Ws[k*64 + (tx<<2)]);
        float ws4[4] = {wv.x, wv.y, wv.z, wv.w};
        #pragma unroll
        for (int d = 0; d < 4; ++d) {
            u64 wd; PKDUP(wd, ws4[d]);
            FMA2(acc[0][d], a01.x, wd);
            FMA2(acc[1][d], a01.y, wd);
            FMA2(acc[2][d], a23.x, wd);
            FMA2(acc[3][d], a23.y, wd);
        }
    }

    float o[8][4];
    #pragma unroll
    for (int i = 0; i < 4; ++i)
        #pragma unroll
        for (int d = 0; d < 4; ++d)
            UNPK(o[2*i][d], o[2*i+1][d], acc[i][d]);
    #pragma unroll
    for (int i = 0; i < 8; ++i)
        #pragma unroll
        for (int j = 0; j < 4; ++j)
            o[i][j] = fmaxf(o[i][j] + bs[(tx<<2)+j], 0.0f) * scale;

    if (blockIdx.y == 0) {
        // Q natural [row][f], tf32-rounded, float4 stores
        #pragma unroll
        for (int i = 0; i < 8; ++i) {
            int r = r0 + rbase + i;
            float4 pv;
            pv.x = __uint_as_float(tf32r(o[i][0]));
            pv.y = __uint_as_float(tf32r(o[i][1]));
            pv.z = __uint_as_float(tf32r(o[i][2]));
            pv.w = __uint_as_float(tf32r(o[i][3]));
            *reinterpret_cast<float4*>(&g_Q[(size_t)r*64 + (tx<<2)]) = pv;
        }
    } else if (blockIdx.y == 1) {
        // K fragment-packed: tile = ty*8+(tx>>1); fidx = tile*64 + (i*4+j)*2 + (tx&1)
        float* base = g_K + (size_t)bt*8192 + (size_t)(ty*8 + (tx>>1))*64 + (tx & 1);
        #pragma unroll
        for (int i = 0; i < 8; ++i)
            #pragma unroll
            for (int j = 0; j < 4; ++j)
                base[(i*4 + j)*2] = __uint_as_float(tf32r(o[i][j]));
    } else {
        // V fragment-packed: fidx = tile*64 + (((tx&1)*4+j)*4 + (i&3))*2 + ((i>>2)&1)
        float* base = g_V + (size_t)bt*8192 + (size_t)(ty*8 + (tx>>1))*64;
        #pragma unroll
        for (int i = 0; i < 8; ++i)
            #pragma unroll
            for (int j = 0; j < 4; ++j)
                base[(((tx&1)*4 + j)*4 + (i&3))*2 + ((i>>2)&1)] =
                    __uint_as_float(tf32r(o[i][j]));
    }
}

// ---------------------------------------------------------------------------
// Kernel 2: tensor-core (mma.sync tf32) fused lag-attention + out-projection.
// grid = B*T*2 (one per (bt,half)), 128 threads (4 warps, M=16 rows each).
// 32-key chunks; K/V triple-buffered cp.async; 1 barrier + 1 wait per chunk.
// P never touches smem: C-frag -> A-frag via warp shuffles.
// smem: K0..K2 (3x8KB) + V0..V2 (3x8KB) = 48KB; Wo overlays for epilogue.
// ---------------------------------------------------------------------------
#define SAF_K 0        // float offsets: K bufs at 0,2048,4096
#define SAF_V 6144     // V bufs at 6144,8192,10240
#define SMEM_ATTN (12288*4)   // 48 KB -> 4 CTAs/SM

__global__ __launch_bounds__(128, 4) void attn_kernel(
    const float* __restrict__ bo, float* __restrict__ out)
{
    extern __shared__ float sm[];

    const int gid  = blockIdx.x;
    const int half = gid & 1;
    const int bt   = gid >> 1;
    const int t_   = bt & (Tdim - 1);
    const int tid  = threadIdx.x;
    const int lane = tid & 31;
    const int w    = tid >> 5;
    const int g    = lane >> 2;
    const int t    = lane & 3;
    const int src0 = (lane & ~3) | (t >> 1);
    const int src1 = src0 + 2;
    const int odd  = t & 1;

    const int nvalid  = (t_ + 1 < LAGn) ? (t_ + 1) : LAGn;
    const int nchunks = nvalid * 4;

    const uint32_t sK = smem_u32(sm + SAF_K);
    const uint32_t sV = smem_u32(sm + SAF_V);

    // ---- Q A-fragments: resident in registers for the whole kernel ----
    uint32_t qa[8][4];
    {
        const float* Qb = g_Q + ((size_t)bt*128 + half*64 + w*16) * 64;
        #pragma unroll
        for (int kt = 0; kt < 8; ++kt) {
            qa[kt][0] = __float_as_uint(Qb[(size_t)g      *64 + kt*8 + t    ]);
            qa[kt][1] = __float_as_uint(Qb[(size_t)(g+8)  *64 + kt*8 + t    ]);
            qa[kt][2] = __float_as_uint(Qb[(size_t)g      *64 + kt*8 + t + 4]);
            qa[kt][3] = __float_as_uint(Qb[(size_t)(g+8)  *64 + kt*8 + t + 4]);
        }
    }

    // ---- prologue: G0 = {K0,V0}, G1 = {K1,V1} ----
    #pragma unroll
    for (int jc = 0; jc < 2; ++jc) {
        const float* Kg = g_K + (size_t)bt*8192 + jc*2048;   // lag 0 chunks 0,1
        const float* Vg = g_V + (size_t)bt*8192 + jc*2048;
        #pragma unroll
        for (int q = 0; q < 4; ++q) {
            int idx = tid + q * 128;   // 0..511
            CPA16(sK + (uint32_t)(jc*2048 + idx*4)*4, Kg + idx*4);
            CPA16(sV + (uint32_t)(jc*2048 + idx*4)*4, Vg + idx*4);
        }
        CPA_COMMIT();
    }

    float agg[8][4];
    #pragma unroll
    for (int nt = 0; nt < 8; ++nt)
        #pragma unroll
        for (int r = 0; r < 4; ++r) agg[nt][r] = 0.0f;
    float dsum0 = 0.0f, dsum1 = 0.0f;

    for (int ic = 0; ic < nchunks; ++ic) {
        CPA_WAIT1();        // G(ic) complete (G(ic+1) pending)
        __syncthreads();    // all warps finished chunk ic-1 -> buf (ic+2)%3 free

        // Prefetch chunk ic+2 into buffer (ic+2)%3 (always commit a group).
        if (ic + 2 < nchunks) {
            const int jc = ic + 2;
            const int bufo = (jc % 3) * 2048;
            const float* Kg = g_K + (size_t)(bt - (jc>>2))*8192 + (jc&3)*2048;
            const float* Vg = g_V + (size_t)(bt - (jc>>2))*8192 + (jc&3)*2048;
            #pragma unroll
            for (int q = 0; q < 4; ++q) {
                int idx = tid + q * 128;
                CPA16(sK + (uint32_t)(bufo + idx*4)*4, Kg + idx*4);
                CPA16(sV + (uint32_t)(bufo + idx*4)*4, Vg + idx*4);
            }
        }
        CPA_COMMIT();

        const float* Kb = sm + SAF_K + (ic % 3) * 2048;
        const float* Vb = sm + SAF_V + (ic % 3) * 2048;

        // ---- GEMM1: S(16x32) = Q(16x64) * K^T ----
        float sc[4][4];
        #pragma unroll
        for (int nt = 0; nt < 4; ++nt)
            #pragma unroll
            for (int r = 0; r < 4; ++r) sc[nt][r] = 0.0f;

        #pragma unroll
        for (int kt = 0; kt < 8; ++kt) {
            #pragma unroll
            for (int nt = 0; nt < 4; ++nt) {
                uint2 b = *reinterpret_cast<const uint2*>(&Kb[((nt*8 + kt)*32 + lane)*2]);
                MMA(sc[nt], qa[kt], b.x, b.y);
            }
        }

        // ---- exp2 in registers + denominator partials ----
        #pragma unroll
        for (int nt = 0; nt < 4; ++nt) {
            float e0, e1, e2, e3;
            EX2(e0, sc[nt][0]); EX2(e1, sc[nt][1]);
            EX2(e2, sc[nt][2]); EX2(e3, sc[nt][3]);
            sc[nt][0] = e0; sc[nt][1] = e1; sc[nt][2] = e2; sc[nt][3] = e3;
            dsum0 += e0 + e1;
            dsum1 += e2 + e3;
        }

        // ---- GEMM2: agg(16x64) += P(16x32) * V(32x64) ----
        #pragma unroll
        for (int kt = 0; kt < 4; ++kt) {
            uint32_t pa[4];
            c2a(sc[kt], pa, src0, src1, odd);
            #pragma unroll
            for (int nt = 0; nt < 8; ++nt) {
                uint2 b = *reinterpret_cast<const uint2*>(&Vb[((kt*8 + nt)*32 + lane)*2]);
                MMA(agg[nt], pa, b.x, b.y);
            }
        }
    }

    // ---- denominators: reduce across the 4 lanes of each row group ----
    const float padadd = (float)(LAGn - nvalid) * 128.0f;   // 2^0 per padded key
    dsum0 += __shfl_xor_sync(0xffffffffu, dsum0, 1);
    dsum0 += __shfl_xor_sync(0xffffffffu, dsum0, 2);
    dsum1 += __shfl_xor_sync(0xffffffffu, dsum1, 1);
    dsum1 += __shfl_xor_sync(0xffffffffu, dsum1, 2);
    const float inv0 = 1.0f / (dsum0 + padadd);
    const float inv1 = 1.0f / (dsum1 + padadd);
    #pragma unroll
    for (int nt = 0; nt < 8; ++nt) {
        agg[nt][0] *= inv0; agg[nt][1] *= inv0;
        agg[nt][2] *= inv1; agg[nt][3] *= inv1;
    }

    // ---- load packed Wo into smem (overlays K/V buffers) ----
    CPA_WAIT0();
    __syncthreads();
    {
        const float* Wg = g_WoP;
        const uint32_t sW = smem_u32(sm);
        #pragma unroll
        for (int q = 0; q < 16; ++q) {
            int idx = tid + q * 128;   // 0..2047 -> 8192 floats
            CPA16(sW + (uint32_t)idx*16, Wg + idx*4);
        }
        CPA_COMMIT();
        CPA_WAIT0();
    }
    __syncthreads();

    // ---- epilogue: out = relu([Q | agg] @ Wo + bo), all tensor-core ----
    float ec[8][4];
    #pragma unroll
    for (int nt = 0; nt < 8; ++nt)
        #pragma unroll
        for (int r = 0; r < 4; ++r) ec[nt][r] = 0.0f;

    #pragma unroll
    for (int kt = 0; kt < 16; ++kt) {
        uint32_t a[4];
        if (kt < 8) {
            a[0] = qa[kt][0]; a[1] = qa[kt][1]; a[2] = qa[kt][2]; a[3] = qa[kt][3];
        } else {
            c2a(agg[kt-8], a, src0, src1, odd);
        }
        #pragma unroll
        for (int nt = 0; nt < 8; ++nt) {
            uint2 b = *reinterpret_cast<const uint2*>(&sm[((kt*8 + nt)*32 + lane)*2]);
            MMA(ec[nt], a, b.x, b.y);
        }
    }

    {
        const size_t rowA = (size_t)bt*128 + half*64 + w*16 + g;
        #pragma unroll
        for (int nt = 0; nt < 8; ++nt) {
            int d0 = nt*8 + 2*t;
            float2 bv = *reinterpret_cast<const float2*>(&bo[d0]);
            float2 o0, o1;
            o0.x = fmaxf(ec[nt][0] + bv.x, 0.0f);
            o0.y = fmaxf(ec[nt][1] + bv.y, 0.0f);
            o1.x = fmaxf(ec[nt][2] + bv.x, 0.0f);
            o1.y = fmaxf(ec[nt][3] + bv.y, 0.0f);
            *reinterpret_cast<float2*>(&out[rowA*64 + d0])       = o0;
            *reinterpret_cast<float2*>(&out[(rowA+8)*64 + d0])   = o1;
        }
    }
}

// ---------------------------------------------------------------------------
extern "C" void kernel_launch(void* const* d_in, const int* in_sizes, int n_in,
                              void* d_out, int out_size)
{
    const float* X  = (const float*)d_in[0];
    const float* Wq = (const float*)d_in[1];
    const float* bq = (const float*)d_in[2];
    const float* Wk = (const float*)d_in[3];
    const float* bk = (const float*)d_in[4];
    const float* Wv = (const float*)d_in[5];
    const float* bv = (const float*)d_in[6];
    const float* Wo = (const float*)d_in[7];
    const float* bo = (const float*)d_in[8];
    float* out = (float*)d_out;

    cudaFuncSetAttribute(attn_kernel,
                         cudaFuncAttributeMaxDynamicSharedMemorySize, SMEM_ATTN);

    pack_wo_kernel<<<1, 128>>>(Wo);
    qkv_kernel<<<dim3(Bdim*Tdim, 3, 1), 256>>>(X, Wq, bq, Wk, bk, Wv, bv);
    attn_kernel<<<Bdim*Tdim*2, 128, SMEM_ATTN>>>(bo, out);
}

// round 15
// speedup vs baseline: 2.9132x; 1.1989x over previous
#include <cuda_runtime.h>
#include <cstdint>

// Problem constants
#define Bdim 8
#define Tdim 64
#define Ndim 128
#define Ddim 64
#define LAGn 8
#define ROWS (Bdim*Tdim*Ndim)   // 65536

typedef unsigned long long u64;

// Scratch (no cudaMalloc allowed)
// g_Q : natural [bt*128 + n][f], tf32-rounded                  (A-frags GEMM1/epilogue)
// g_K : fragment-packed per bt, scaled 0.125*log2e, tf32       (B-frags GEMM1)
//       K[key][f] -> ((key>>3)*8+(f>>3))*64 + ((key&7)*4+(f&3))*2 + ((f>>2)&1)
// g_V : fragment-packed per bt, tf32                            (B-frags GEMM2)
//       V[key][d] -> ((key>>3)*8+(d>>3))*64 + ((d&7)*4+(key&3))*2 + ((key>>2)&1)
// g_WoP: fragment-packed Wo (128x64), tf32                      (B-frags epilogue)
__device__ float g_Q[ROWS*Ddim];
__device__ float g_K[ROWS*Ddim];
__device__ float g_V[ROWS*Ddim];
__device__ float g_WoP[128*64];

#define EX2(y, x)        asm("ex2.approx.f32 %0, %1;" : "=f"(y) : "f"(x))

// cp.async helpers
#define CPA16(d, s)   asm volatile("cp.async.cg.shared.global [%0], [%1], 16;" :: "r"(d), "l"(s) : "memory")
#define CPA_COMMIT()  asm volatile("cp.async.commit_group;" ::: "memory")
#define CPA_WAIT0()   asm volatile("cp.async.wait_group 0;" ::: "memory")
#define CPA_WAIT1()   asm volatile("cp.async.wait_group 1;" ::: "memory")

__device__ __forceinline__ uint32_t smem_u32(const void* p) {
    uint32_t a;
    asm("{ .reg .u64 t; cvta.to.shared.u64 t, %1; cvt.u32.u64 %0, t; }" : "=r"(a) : "l"(p));
    return a;
}
__device__ __forceinline__ uint32_t tf32r(float f) {
    uint32_t u;
    asm("cvt.rna.tf32.f32 %0, %1;" : "=r"(u) : "f"(f));
    return u;
}

// tf32 tensor-core mma (classic mma.sync -> HMMA on sm_103; NOT 103a-gated)
#define MMA(d, a, b0, b1) \
    asm volatile("mma.sync.aligned.m16n8k8.row.col.f32.tf32.tf32.f32 " \
        "{%0,%1,%2,%3}, {%4,%5,%6,%7}, {%8,%9}, {%0,%1,%2,%3};" \
        : "+f"((d)[0]), "+f"((d)[1]), "+f"((d)[2]), "+f"((d)[3]) \
        : "r"((a)[0]), "r"((a)[1]), "r"((a)[2]), "r"((a)[3]), "r"(b0), "r"(b1))

// C-fragment (m16n8 f32) -> A-fragment (m16k8 tf32) permute via shuffles.
__device__ __forceinline__ void c2a(const float* c, uint32_t* a, int src0, int src1, int odd) {
    float e0 = __shfl_sync(0xffffffffu, c[0], src0);
    float e1 = __shfl_sync(0xffffffffu, c[1], src0);
    float f0 = __shfl_sync(0xffffffffu, c[0], src1);
    float f1 = __shfl_sync(0xffffffffu, c[1], src1);
    float g0 = __shfl_sync(0xffffffffu, c[2], src0);
    float g1 = __shfl_sync(0xffffffffu, c[3], src0);
    float h0 = __shfl_sync(0xffffffffu, c[2], src1);
    float h1 = __shfl_sync(0xffffffffu, c[3], src1);
    a[0] = tf32r(odd ? e1 : e0);
    a[2] = tf32r(odd ? f1 : f0);
    a[1] = tf32r(odd ? g1 : g0);
    a[3] = tf32r(odd ? h1 : h0);
}

// ---------------------------------------------------------------------------
// Kernel 1: tensor-core QKV projection. grid = 512, 256 threads (8 warps).
// One CTA per bt computes Q, K, V sharing one X tile. Also packs Wo (bt==0).
// Xs: [128 row][68 f] stride-68 -> A-frag LDS bank == lane (conflict-free).
// Wp: Wq/Wk/Wv in B-fragment layout.
// ---------------------------------------------------------------------------
#define QS_X 0                 // 128*68 = 8704 floats
#define QS_W 8704              // 3*4096 = 12288 floats
#define QS_B 20992             // 3*64 bias
#define QKV_SMEM ((21184)*4)   // ~84.7 KB -> 2 CTAs/SM

__global__ __launch_bounds__(256, 2) void qkv_kernel(
    const float* __restrict__ X,
    const float* __restrict__ Wq, const float* __restrict__ bq,
    const float* __restrict__ Wk, const float* __restrict__ bk,
    const float* __restrict__ Wv, const float* __restrict__ bv,
    const float* __restrict__ Wo)
{
    extern __shared__ float qs[];
    float* Xs = qs + QS_X;
    float* Wp = qs + QS_W;
    float* bs = qs + QS_B;

    const int bt  = blockIdx.x;
    const int tid = threadIdx.x;

    // Side job: CTA 0 packs Wo into fragment layout (independent of X/W smem).
    if (bt == 0) {
        #pragma unroll
        for (int q = 0; q < 8; ++q) {
            int idx4 = tid + q * 256;            // 0..2047
            float4 v = reinterpret_cast<const float4*>(Wo)[idx4];
            int gidx = idx4 * 4;
            int c = gidx >> 6, d0 = gidx & 63;
            float vv[4] = {v.x, v.y, v.z, v.w};
            #pragma unroll
            for (int e = 0; e < 4; ++e) {
                int d = d0 + e;
                int fidx = ((c>>3)*8 + (d>>3))*64 + ((d&7)*4 + (c&3))*2 + ((c>>2)&1);
                g_WoP[fidx] = __uint_as_float(tf32r(vv[e]));
            }
        }
    }

    // ---- load X tile (tf32-rounded, stride 68) + pack W tiles + bias ----
    {
        const float4* Xg = reinterpret_cast<const float4*>(X + (size_t)bt * 128 * 64);
        #pragma unroll
        for (int q = 0; q < 8; ++q) {
            int idx4 = tid + q * 256;            // 0..2047
            int row = idx4 >> 4, c4 = (idx4 & 15) << 2;
            float4 v = Xg[idx4];
            float4 pv;
            pv.x = __uint_as_float(tf32r(v.x));
            pv.y = __uint_as_float(tf32r(v.y));
            pv.z = __uint_as_float(tf32r(v.z));
            pv.w = __uint_as_float(tf32r(v.w));
            *reinterpret_cast<float4*>(&Xs[row*68 + c4]) = pv;
        }
        const float* Wsrc[3] = {Wq, Wk, Wv};
        #pragma unroll
        for (int w3 = 0; w3 < 3; ++w3) {
            const float4* Wg = reinterpret_cast<const float4*>(Wsrc[w3]);
            #pragma unroll
            for (int q = 0; q < 4; ++q) {
                int idx4 = tid + q * 256;        // 0..1023
                float4 v = Wg[idx4];
                int gidx = idx4 * 4;
                int f = gidx >> 6, d0 = gidx & 63;
                float vv[4] = {v.x, v.y, v.z, v.w};
                #pragma unroll
                for (int e = 0; e < 4; ++e) {
                    int d = d0 + e;
                    int fidx = ((d>>3)*8 + (f>>3))*64 + ((d&7)*4 + (f&3))*2 + ((f>>2)&1);
                    Wp[w3*4096 + fidx] = __uint_as_float(tf32r(vv[e]));
                }
            }
        }
        if (tid < 64)        bs[tid]       = bq[tid];
        else if (tid < 128)  bs[tid]       = bk[tid-64];
        else if (tid < 192)  bs[tid]       = bv[tid-128];
    }
    __syncthreads();

    const int lane = tid & 31;
    const int w    = tid >> 5;          // 0..7 -> rows w*16..+15
    const int g    = lane >> 2;
    const int t    = lane & 3;

    // A-fragments of X (shared across Q/K/V)
    uint32_t xa[8][4];
    {
        const float* Xr = Xs + (w*16)*68;
        #pragma unroll
        for (int kt = 0; kt < 8; ++kt) {
            xa[kt][0] = __float_as_uint(Xr[g    *68 + kt*8 + t    ]);
            xa[kt][1] = __float_as_uint(Xr[(g+8)*68 + kt*8 + t    ]);
            xa[kt][2] = __float_as_uint(Xr[g    *68 + kt*8 + t + 4]);
            xa[kt][3] = __float_as_uint(Xr[(g+8)*68 + kt*8 + t + 4]);
        }
    }

    const float scale3[3] = {1.0f, 0.125f * 1.4426950408889634f, 1.0f};

    #pragma unroll
    for (int w3 = 0; w3 < 3; ++w3) {
        float acc[8][4];
        #pragma unroll
        for (int nt = 0; nt < 8; ++nt)
            #pragma unroll
            for (int r = 0; r < 4; ++r) acc[nt][r] = 0.0f;

        const float* Wp3 = Wp + w3*4096;
        #pragma unroll
        for (int kt = 0; kt < 8; ++kt) {
            #pragma unroll
            for (int nt = 0; nt < 8; ++nt) {
                uint2 b = *reinterpret_cast<const uint2*>(&Wp3[((nt*8 + kt)*32 + lane)*2]);
                MMA(acc[nt], xa[kt], b.x, b.y);
            }
        }

        const float sc = scale3[w3];
        #pragma unroll
        for (int nt = 0; nt < 8; ++nt) {
            float b0 = bs[w3*64 + nt*8 + 2*t];
            float b1 = bs[w3*64 + nt*8 + 2*t + 1];
            acc[nt][0] = fmaxf(acc[nt][0] + b0, 0.0f) * sc;
            acc[nt][1] = fmaxf(acc[nt][1] + b1, 0.0f) * sc;
            acc[nt][2] = fmaxf(acc[nt][2] + b0, 0.0f) * sc;
            acc[nt][3] = fmaxf(acc[nt][3] + b1, 0.0f) * sc;
        }

        if (w3 == 0) {
            // Q natural tf32: rows bt*128 + w*16 + g (+8)
            const size_t rowA = (size_t)bt*128 + w*16 + g;
            #pragma unroll
            for (int nt = 0; nt < 8; ++nt) {
                int d0 = nt*8 + 2*t;
                float2 o0, o1;
                o0.x = __uint_as_float(tf32r(acc[nt][0]));
                o0.y = __uint_as_float(tf32r(acc[nt][1]));
                o1.x = __uint_as_float(tf32r(acc[nt][2]));
                o1.y = __uint_as_float(tf32r(acc[nt][3]));
                *reinterpret_cast<float2*>(&g_Q[rowA*64 + d0])     = o0;
                *reinterpret_cast<float2*>(&g_Q[(rowA+8)*64 + d0]) = o1;
            }
        } else if (w3 == 1) {
            // K fragment-packed: key = w*16+g (+8), f = nt*8+2t+j
            float* base = g_K + (size_t)bt*8192;
            #pragma unroll
            for (int nt = 0; nt < 8; ++nt) {
                #pragma unroll
                for (int j = 0; j < 2; ++j) {
                    int f = 2*t + j;
                    int elem = (g*4 + (f&3))*2 + (f>>2);
                    int tile0 = (w*2    )*8 + nt;
                    int tile1 = (w*2 + 1)*8 + nt;
                    base[tile0*64 + elem] = __uint_as_float(tf32r(acc[nt][j]));
                    base[tile1*64 + elem] = __uint_as_float(tf32r(acc[nt][2+j]));
                }
            }
        } else {
            // V fragment-packed: key = w*16+g (+8), d = nt*8+2t+j
            float* base = g_V + (size_t)bt*8192;
            #pragma unroll
            for (int nt = 0; nt < 8; ++nt) {
                #pragma unroll
                for (int j = 0; j < 2; ++j) {
                    int dd = 2*t + j;
                    int elem = (dd*4 + (g&3))*2 + ((g>>2)&1);
                    int tile0 = (w*2    )*8 + nt;
                    int tile1 = (w*2 + 1)*8 + nt;
                    base[tile0*64 + elem] = __uint_as_float(tf32r(acc[nt][j]));
                    base[tile1*64 + elem] = __uint_as_float(tf32r(acc[nt][2+j]));
                }
            }
        }
    }
}

// ---------------------------------------------------------------------------
// Kernel 2: tensor-core fused lag-attention + out-projection.
// grid = 512 (one per bt), 256 threads (8 warps, M=16 rows each, 128 rows).
// 32-key chunks; K/V triple-buffered cp.async; 1 barrier + 1 wait per chunk.
// Each K/V chunk loaded ONCE per bt (was twice in the half-CTA version).
// ---------------------------------------------------------------------------
#define SAF_K 0        // float offsets: K bufs at 0,2048,4096
#define SAF_V 6144     // V bufs at 6144,8192,10240
#define SMEM_ATTN (12288*4)   // 48 KB

__global__ __launch_bounds__(256, 2) void attn_kernel(
    const float* __restrict__ bo, float* __restrict__ out)
{
    extern __shared__ float sm[];

    const int bt   = blockIdx.x;
    const int t_   = bt & (Tdim - 1);
    const int tid  = threadIdx.x;
    const int lane = tid & 31;
    const int w    = tid >> 5;         // 0..7
    const int g    = lane >> 2;
    const int t    = lane & 3;
    const int src0 = (lane & ~3) | (t >> 1);
    const int src1 = src0 + 2;
    const int odd  = t & 1;

    const int nvalid  = (t_ + 1 < LAGn) ? (t_ + 1) : LAGn;
    const int nchunks = nvalid * 4;

    const uint32_t sK = smem_u32(sm + SAF_K);
    const uint32_t sV = smem_u32(sm + SAF_V);

    // ---- Q A-fragments: resident in registers for the whole kernel ----
    uint32_t qa[8][4];
    {
        const float* Qb = g_Q + ((size_t)bt*128 + w*16) * 64;
        #pragma unroll
        for (int kt = 0; kt < 8; ++kt) {
            qa[kt][0] = __float_as_uint(Qb[(size_t)g    *64 + kt*8 + t    ]);
            qa[kt][1] = __float_as_uint(Qb[(size_t)(g+8)*64 + kt*8 + t    ]);
            qa[kt][2] = __float_as_uint(Qb[(size_t)g    *64 + kt*8 + t + 4]);
            qa[kt][3] = __float_as_uint(Qb[(size_t)(g+8)*64 + kt*8 + t + 4]);
        }
    }

    // ---- prologue: G0 = {K0,V0}, G1 = {K1,V1} ----
    #pragma unroll
    for (int jc = 0; jc < 2; ++jc) {
        const float* Kg = g_K + (size_t)bt*8192 + jc*2048;
        const float* Vg = g_V + (size_t)bt*8192 + jc*2048;
        #pragma unroll
        for (int q = 0; q < 2; ++q) {
            int idx = tid + q * 256;   // 0..511
            CPA16(sK + (uint32_t)(jc*2048 + idx*4)*4, Kg + idx*4);
            CPA16(sV + (uint32_t)(jc*2048 + idx*4)*4, Vg + idx*4);
        }
        CPA_COMMIT();
    }

    float agg[8][4];
    #pragma unroll
    for (int nt = 0; nt < 8; ++nt)
        #pragma unroll
        for (int r = 0; r < 4; ++r) agg[nt][r] = 0.0f;
    float dsum0 = 0.0f, dsum1 = 0.0f;

    for (int ic = 0; ic < nchunks; ++ic) {
        CPA_WAIT1();        // G(ic) complete (G(ic+1) pending)
        __syncthreads();    // all warps finished chunk ic-1 -> buf (ic+2)%3 free

        if (ic + 2 < nchunks) {
            const int jc = ic + 2;
            const int bufo = (jc % 3) * 2048;
            const float* Kg = g_K + (size_t)(bt - (jc>>2))*8192 + (jc&3)*2048;
            const float* Vg = g_V + (size_t)(bt - (jc>>2))*8192 + (jc&3)*2048;
            #pragma unroll
            for (int q = 0; q < 2; ++q) {
                int idx = tid + q * 256;
                CPA16(sK + (uint32_t)(bufo + idx*4)*4, Kg + idx*4);
                CPA16(sV + (uint32_t)(bufo + idx*4)*4, Vg + idx*4);
            }
        }
        CPA_COMMIT();

        const float* Kb = sm + SAF_K + (ic % 3) * 2048;
        const float* Vb = sm + SAF_V + (ic % 3) * 2048;

        // ---- GEMM1: S(16x32) = Q(16x64) * K^T ----
        float sc[4][4];
        #pragma unroll
        for (int nt = 0; nt < 4; ++nt)
            #pragma unroll
            for (int r = 0; r < 4; ++r) sc[nt][r] = 0.0f;

        #pragma unroll
        for (int kt = 0; kt < 8; ++kt) {
            #pragma unroll
            for (int nt = 0; nt < 4; ++nt) {
                uint2 b = *reinterpret_cast<const uint2*>(&Kb[((nt*8 + kt)*32 + lane)*2]);
                MMA(sc[nt], qa[kt], b.x, b.y);
            }
        }

        // ---- exp2 in registers + denominator partials ----
        #pragma unroll
        for (int nt = 0; nt < 4; ++nt) {
            float e0, e1, e2, e3;
            EX2(e0, sc[nt][0]); EX2(e1, sc[nt][1]);
            EX2(e2, sc[nt][2]); EX2(e3, sc[nt][3]);
            sc[nt][0] = e0; sc[nt][1] = e1; sc[nt][2] = e2; sc[nt][3] = e3;
            dsum0 += e0 + e1;
            dsum1 += e2 + e3;
        }

        // ---- GEMM2: agg(16x64) += P(16x32) * V(32x64) ----
        #pragma unroll
        for (int kt = 0; kt < 4; ++kt) {
            uint32_t pa[4];
            c2a(sc[kt], pa, src0, src1, odd);
            #pragma unroll
            for (int nt = 0; nt < 8; ++nt) {
                uint2 b = *reinterpret_cast<const uint2*>(&Vb[((kt*8 + nt)*32 + lane)*2]);
                MMA(agg[nt], pa, b.x, b.y);
            }
        }
    }

    // ---- denominators ----
    const float padadd = (float)(LAGn - nvalid) * 128.0f;
    dsum0 += __shfl_xor_sync(0xffffffffu, dsum0, 1);
    dsum0 += __shfl_xor_sync(0xffffffffu, dsum0, 2);
    dsum1 += __shfl_xor_sync(0xffffffffu, dsum1, 1);
    dsum1 += __shfl_xor_sync(0xffffffffu, dsum1, 2);
    const float inv0 = 1.0f / (dsum0 + padadd);
    const float inv1 = 1.0f / (dsum1 + padadd);
    #pragma unroll
    for (int nt = 0; nt < 8; ++nt) {
        agg[nt][0] *= inv0; agg[nt][1] *= inv0;
        agg[nt][2] *= inv1; agg[nt][3] *= inv1;
    }

    // ---- load packed Wo into smem (overlays K/V buffers) ----
    CPA_WAIT0();
    __syncthreads();
    {
        const uint32_t sW = smem_u32(sm);
        #pragma unroll
        for (int q = 0; q < 8; ++q) {
            int idx = tid + q * 256;   // 0..2047 -> 8192 floats
            CPA16(sW + (uint32_t)idx*16, g_WoP + idx*4);
        }
        CPA_COMMIT();
        CPA_WAIT0();
    }
    __syncthreads();

    // ---- epilogue: out = relu([Q | agg] @ Wo + bo), all tensor-core ----
    float ec[8][4];
    #pragma unroll
    for (int nt = 0; nt < 8; ++nt)
        #pragma unroll
        for (int r = 0; r < 4; ++r) ec[nt][r] = 0.0f;

    #pragma unroll
    for (int kt = 0; kt < 16; ++kt) {
        uint32_t a[4];
        if (kt < 8) {
            a[0] = qa[kt][0]; a[1] = qa[kt][1]; a[2] = qa[kt][2]; a[3] = qa[kt][3];
        } else {
            c2a(agg[kt-8], a, src0, src1, odd);
        }
        #pragma unroll
        for (int nt = 0; nt < 8; ++nt) {
            uint2 b = *reinterpret_cast<const uint2*>(&sm[((kt*8 + nt)*32 + lane)*2]);
            MMA(ec[nt], a, b.x, b.y);
        }
    }

    {
        const size_t rowA = (size_t)bt*128 + w*16 + g;
        #pragma unroll
        for (int nt = 0; nt < 8; ++nt) {
            int d0 = nt*8 + 2*t;
            float2 bv = *reinterpret_cast<const float2*>(&bo[d0]);
            float2 o0, o1;
            o0.x = fmaxf(ec[nt][0] + bv.x, 0.0f);
            o0.y = fmaxf(ec[nt][1] + bv.y, 0.0f);
            o1.x = fmaxf(ec[nt][2] + bv.x, 0.0f);
            o1.y = fmaxf(ec[nt][3] + bv.y, 0.0f);
            *reinterpret_cast<float2*>(&out[rowA*64 + d0])     = o0;
            *reinterpret_cast<float2*>(&out[(rowA+8)*64 + d0]) = o1;
        }
    }
}

// ---------------------------------------------------------------------------
extern "C" void kernel_launch(void* const* d_in, const int* in_sizes, int n_in,
                              void* d_out, int out_size)
{
    const float* X  = (const float*)d_in[0];
    const float* Wq = (const float*)d_in[1];
    const float* bq = (const float*)d_in[2];
    const float* Wk = (const float*)d_in[3];
    const float* bk = (const float*)d_in[4];
    const float* Wv = (const float*)d_in[5];
    const float* bv = (const float*)d_in[6];
    const float* Wo = (const float*)d_in[7];
    const float* bo = (const float*)d_in[8];
    float* out = (float*)d_out;

    cudaFuncSetAttribute(qkv_kernel,
                         cudaFuncAttributeMaxDynamicSharedMemorySize, QKV_SMEM);
    cudaFuncSetAttribute(attn_kernel,
                         cudaFuncAttributeMaxDynamicSharedMemorySize, SMEM_ATTN);

    qkv_kernel<<<Bdim*Tdim, 256, QKV_SMEM>>>(X, Wq, bq, Wk, bk, Wv, bv, Wo);
    attn_kernel<<<Bdim*Tdim, 256, SMEM_ATTN>>>(bo, out);
}

// round 17
// speedup vs baseline: 4.0418x; 1.3874x over previous
#include <cuda_runtime.h>
#include <cstdint>

// Problem constants
#define Bdim 8
#define Tdim 64
#define Ndim 128
#define Ddim 64
#define LAGn 8
#define ROWS (Bdim*Tdim*Ndim)   // 65536

// Scratch (no cudaMalloc allowed)
// g_Q  : natural [row][64] tf32  (epilogue A-frags)
// g_Qb : [row][32] bf16x2 pairs  (GEMM1 A-frags)
// g_Kb : per bt 4096 u32 (4 chunks x 16 tiles x 64) bf16 B-frags, GEMM1
// g_Vb : per bt 4096 u32 bf16 B-frags, GEMM2
// g_WoP: 8192 floats tf32 fragment-packed Wo (epilogue B-frags)
__device__ float    g_Q  [ROWS*Ddim];
__device__ uint32_t g_Qb [ROWS*32];
__device__ uint32_t g_Kb [ROWS*32];
__device__ uint32_t g_Vb [ROWS*32];
__device__ float    g_WoP[128*64];

#define EX2(y, x)        asm("ex2.approx.f32 %0, %1;" : "=f"(y) : "f"(x))
#define PKBF(r, lo, hi)  asm("cvt.rn.bf16x2.f32 %0, %2, %1;" : "=r"(r) : "f"(lo), "f"(hi))

// cp.async helpers
#define CPA16(d, s)   asm volatile("cp.async.cg.shared.global [%0], [%1], 16;" :: "r"(d), "l"(s) : "memory")
#define CPA_COMMIT()  asm volatile("cp.async.commit_group;" ::: "memory")
#define CPA_WAIT0()   asm volatile("cp.async.wait_group 0;" ::: "memory")
#define CPA_WAIT1()   asm volatile("cp.async.wait_group 1;" ::: "memory")

__device__ __forceinline__ uint32_t smem_u32(const void* p) {
    uint32_t a;
    asm("{ .reg .u64 t; cvta.to.shared.u64 t, %1; cvt.u32.u64 %0, t; }" : "=r"(a) : "l"(p));
    return a;
}
__device__ __forceinline__ uint32_t tf32r(float f) {
    uint32_t u;
    asm("cvt.rna.tf32.f32 %0, %1;" : "=r"(u) : "f"(f));
    return u;
}

// tf32 mma m16n8k8 (qkv + epilogue)
#define MMA(d, a, b0, b1) \
    asm volatile("mma.sync.aligned.m16n8k8.row.col.f32.tf32.tf32.f32 " \
        "{%0,%1,%2,%3}, {%4,%5,%6,%7}, {%8,%9}, {%0,%1,%2,%3};" \
        : "+f"((d)[0]), "+f"((d)[1]), "+f"((d)[2]), "+f"((d)[3]) \
        : "r"((a)[0]), "r"((a)[1]), "r"((a)[2]), "r"((a)[3]), "r"(b0), "r"(b1))

// bf16 mma m16n8k16 (attention core)
#define MMAB(d, a, b0, b1) \
    asm volatile("mma.sync.aligned.m16n8k16.row.col.f32.bf16.bf16.f32 " \
        "{%0,%1,%2,%3}, {%4,%5,%6,%7}, {%8,%9}, {%0,%1,%2,%3};" \
        : "+f"((d)[0]), "+f"((d)[1]), "+f"((d)[2]), "+f"((d)[3]) \
        : "r"((a)[0]), "r"((a)[1]), "r"((a)[2]), "r"((a)[3]), "r"(b0), "r"(b1))

// C-fragment (m16n8 f32) -> tf32 A-fragment (m16k8) via shuffles (R15-validated).
__device__ __forceinline__ void c2a(const float* c, uint32_t* a, int src0, int src1, int odd) {
    float e0 = __shfl_sync(0xffffffffu, c[0], src0);
    float e1 = __shfl_sync(0xffffffffu, c[1], src0);
    float f0 = __shfl_sync(0xffffffffu, c[0], src1);
    float f1 = __shfl_sync(0xffffffffu, c[1], src1);
    float g0 = __shfl_sync(0xffffffffu, c[2], src0);
    float g1 = __shfl_sync(0xffffffffu, c[3], src0);
    float h0 = __shfl_sync(0xffffffffu, c[2], src1);
    float h1 = __shfl_sync(0xffffffffu, c[3], src1);
    a[0] = tf32r(odd ? e1 : e0);
    a[2] = tf32r(odd ? f1 : f0);
    a[1] = tf32r(odd ? g1 : g0);
    a[3] = tf32r(odd ? h1 : h0);
}

// ---------------------------------------------------------------------------
// Kernel 1: tensor-core QKV projection (tf32 compute). grid = 512, 256 thr.
// Outputs: Q tf32 natural + Q bf16 pairs; K/V bf16 B-frags. bt==0 packs Wo (tf32).
// ---------------------------------------------------------------------------
#define QS_X 0                 // 128*68 floats (reused as V staging)
#define QS_W 8704              // 3*4096 floats
#define QS_B 20992             // 3*64 bias
#define QKV_SMEM ((21184)*4)   // ~84.7 KB -> 2 CTAs/SM

__global__ __launch_bounds__(256, 2) void qkv_kernel(
    const float* __restrict__ X,
    const float* __restrict__ Wq, const float* __restrict__ bq,
    const float* __restrict__ Wk, const float* __restrict__ bk,
    const float* __restrict__ Wv, const float* __restrict__ bv,
    const float* __restrict__ Wo)
{
    extern __shared__ float qs[];
    float* Xs = qs + QS_X;
    float* Wp = qs + QS_W;
    float* bs = qs + QS_B;

    const int bt  = blockIdx.x;
    const int tid = threadIdx.x;

    // Side job: CTA 0 packs Wo into tf32 B-fragment layout (R15-validated).
    if (bt == 0) {
        #pragma unroll
        for (int q = 0; q < 8; ++q) {
            int idx4 = tid + q * 256;            // 0..2047
            float4 v = reinterpret_cast<const float4*>(Wo)[idx4];
            int gidx = idx4 * 4;
            int c = gidx >> 6, d0 = gidx & 63;
            float vv[4] = {v.x, v.y, v.z, v.w};
            #pragma unroll
            for (int e = 0; e < 4; ++e) {
                int d = d0 + e;
                int fidx = ((c>>3)*8 + (d>>3))*64 + ((d&7)*4 + (c&3))*2 + ((c>>2)&1);
                g_WoP[fidx] = __uint_as_float(tf32r(vv[e]));
            }
        }
    }

    // ---- load X tile (tf32, stride 68) + pack W tiles (tf32 B-frags) ----
    {
        const float4* Xg = reinterpret_cast<const float4*>(X + (size_t)bt * 128 * 64);
        #pragma unroll
        for (int q = 0; q < 8; ++q) {
            int idx4 = tid + q * 256;
            int row = idx4 >> 4, c4 = (idx4 & 15) << 2;
            float4 v = Xg[idx4];
            float4 pv;
            pv.x = __uint_as_float(tf32r(v.x));
            pv.y = __uint_as_float(tf32r(v.y));
            pv.z = __uint_as_float(tf32r(v.z));
            pv.w = __uint_as_float(tf32r(v.w));
            *reinterpret_cast<float4*>(&Xs[row*68 + c4]) = pv;
        }
        const float* Wsrc[3] = {Wq, Wk, Wv};
        #pragma unroll
        for (int w3 = 0; w3 < 3; ++w3) {
            const float4* Wg = reinterpret_cast<const float4*>(Wsrc[w3]);
            #pragma unroll
            for (int q = 0; q < 4; ++q) {
                int idx4 = tid + q * 256;
                float4 v = Wg[idx4];
                int gidx = idx4 * 4;
                int f = gidx >> 6, d0 = gidx & 63;
                float vv[4] = {v.x, v.y, v.z, v.w};
                #pragma unroll
                for (int e = 0; e < 4; ++e) {
                    int d = d0 + e;
                    int fidx = ((d>>3)*8 + (f>>3))*64 + ((d&7)*4 + (f&3))*2 + ((f>>2)&1);
                    Wp[w3*4096 + fidx] = __uint_as_float(tf32r(vv[e]));
                }
            }
        }
        if (tid < 64)        bs[tid] = bq[tid];
        else if (tid < 128)  bs[tid] = bk[tid-64];
        else if (tid < 192)  bs[tid] = bv[tid-128];
    }
    __syncthreads();

    const int lane = tid & 31;
    const int w    = tid >> 5;
    const int g    = lane >> 2;
    const int t    = lane & 3;

    // A-fragments of X (tf32, m16n8k8), shared across Q/K/V
    uint32_t xa[8][4];
    {
        const float* Xr = Xs + (w*16)*68;
        #pragma unroll
        for (int kt = 0; kt < 8; ++kt) {
            xa[kt][0] = __float_as_uint(Xr[g    *68 + kt*8 + t    ]);
            xa[kt][1] = __float_as_uint(Xr[(g+8)*68 + kt*8 + t    ]);
            xa[kt][2] = __float_as_uint(Xr[g    *68 + kt*8 + t + 4]);
            xa[kt][3] = __float_as_uint(Xr[(g+8)*68 + kt*8 + t + 4]);
        }
    }

    const float scale3[3] = {1.0f, 0.125f * 1.4426950408889634f, 1.0f};

    #pragma unroll
    for (int w3 = 0; w3 < 3; ++w3) {
        float acc[8][4];
        #pragma unroll
        for (int nt = 0; nt < 8; ++nt)
            #pragma unroll
            for (int r = 0; r < 4; ++r) acc[nt][r] = 0.0f;

        const float* Wp3 = Wp + w3*4096;
        #pragma unroll
        for (int kt = 0; kt < 8; ++kt) {
            #pragma unroll
            for (int nt = 0; nt < 8; ++nt) {
                uint2 b = *reinterpret_cast<const uint2*>(&Wp3[((nt*8 + kt)*32 + lane)*2]);
                MMA(acc[nt], xa[kt], b.x, b.y);
            }
        }

        const float sc = scale3[w3];
        #pragma unroll
        for (int nt = 0; nt < 8; ++nt) {
            float b0 = bs[w3*64 + nt*8 + 2*t];
            float b1 = bs[w3*64 + nt*8 + 2*t + 1];
            acc[nt][0] = fmaxf(acc[nt][0] + b0, 0.0f) * sc;
            acc[nt][1] = fmaxf(acc[nt][1] + b1, 0.0f) * sc;
            acc[nt][2] = fmaxf(acc[nt][2] + b0, 0.0f) * sc;
            acc[nt][3] = fmaxf(acc[nt][3] + b1, 0.0f) * sc;
        }

        if (w3 == 0) {
            // Q: bf16 pairs for GEMM1 + tf32 natural for epilogue
            uint32_t* Qb = g_Qb + ((size_t)bt*128 + w*16) * 32;
            const size_t rowA = (size_t)bt*128 + w*16 + g;
            #pragma unroll
            for (int nt = 0; nt < 8; ++nt) {
                uint32_t p01, p23;
                PKBF(p01, acc[nt][0], acc[nt][1]);
                PKBF(p23, acc[nt][2], acc[nt][3]);
                Qb[(size_t)g*32     + nt*4 + t] = p01;
                Qb[(size_t)(g+8)*32 + nt*4 + t] = p23;
                int d0 = nt*8 + 2*t;
                float2 o0, o1;
                o0.x = __uint_as_float(tf32r(acc[nt][0]));
                o0.y = __uint_as_float(tf32r(acc[nt][1]));
                o1.x = __uint_as_float(tf32r(acc[nt][2]));
                o1.y = __uint_as_float(tf32r(acc[nt][3]));
                *reinterpret_cast<float2*>(&g_Q[rowA*64 + d0])     = o0;
                *reinterpret_cast<float2*>(&g_Q[(rowA+8)*64 + d0]) = o1;
            }
        } else if (w3 == 1) {
            // K: bf16 B-frags. key = w*16+g (+8), f = nt*8+2t(+1)
            uint32_t* base = g_Kb + (size_t)bt*4096 + (w>>1)*1024;
            #pragma unroll
            for (int nt = 0; nt < 8; ++nt) {
                uint32_t p01, p23;
                PKBF(p01, acc[nt][0], acc[nt][1]);
                PKBF(p23, acc[nt][2], acc[nt][3]);
                int ftile = nt >> 1, r = nt & 1;
                int kt0 = (2*w) & 3, kt1 = (2*w + 1) & 3;
                base[(kt0*4 + ftile)*64 + (g*4 + t)*2 + r] = p01;
                base[(kt1*4 + ftile)*64 + (g*4 + t)*2 + r] = p23;
            }
        } else {
            // V: stage natural f32, pack bf16 B-frags after sync.
            float* Vst = qs + QS_X;
            #pragma unroll
            for (int nt = 0; nt < 8; ++nt) {
                int d0 = nt*8 + 2*t;
                *reinterpret_cast<float2*>(&Vst[(w*16+g)*64 + d0]) =
                    make_float2(acc[nt][0], acc[nt][1]);
                *reinterpret_cast<float2*>(&Vst[(w*16+g+8)*64 + d0]) =
                    make_float2(acc[nt][2], acc[nt][3]);
            }
        }
    }

    __syncthreads();
    // pack V bf16 B-frags: chunk(4) x tile(16) x lane x r
    {
        const float* Vst = qs + QS_X;
        uint32_t* Vout = g_Vb + (size_t)bt*4096;
        #pragma unroll
        for (int q = 0; q < 16; ++q) {
            int u = tid + q * 256;               // 0..4095
            int cv = u >> 10;
            int tile = (u >> 6) & 15;
            int li = (u >> 1) & 31;
            int r = u & 1;
            int kk = tile >> 3, nt = tile & 7;
            int gb = li >> 2, tb = li & 3;
            int key = cv*32 + kk*16 + 2*tb + 8*r;
            int d = nt*8 + gb;
            float v0 = Vst[key*64 + d];
            float v1 = Vst[(key+1)*64 + d];
            uint32_t pv; PKBF(pv, v0, v1);
            Vout[u] = pv;
        }
    }
}

// ---------------------------------------------------------------------------
// Kernel 2: bf16 attention core + tf32 epilogue.
// grid = 512 (one per bt), 256 threads (8 warps x 16 rows).
// 32-key chunks; triple-buffered cp.async; 1 barrier + 1 wait per chunk.
// smem: K/V bufs 24 KB; tf32 Wo (32 KB) overlays at end -> SMEM 32 KB.
// ---------------------------------------------------------------------------
#define SMEM_ATTN (8192*4)   // 32 KB

__global__ __launch_bounds__(256, 2) void attn_kernel(
    const float* __restrict__ bo, float* __restrict__ out)
{
    extern __shared__ float sm[];
    uint32_t* smu = reinterpret_cast<uint32_t*>(sm);

    const int bt   = blockIdx.x;
    const int t_   = bt & (Tdim - 1);
    const int tid  = threadIdx.x;
    const int lane = tid & 31;
    const int w    = tid >> 5;
    const int g    = lane >> 2;
    const int t    = lane & 3;
    const int src0 = (lane & ~3) | (t >> 1);
    const int src1 = src0 + 2;
    const int odd  = t & 1;

    const int nvalid  = (t_ + 1 < LAGn) ? (t_ + 1) : LAGn;
    const int nchunks = nvalid * 4;

    const uint32_t sK = smem_u32(smu);           // u32 offs 0,1024,2048
    const uint32_t sV = smem_u32(smu + 3072);    // u32 offs 3072,4096,5120

    // ---- Q A-fragments (bf16, m16n8k16) ----
    uint32_t qa[4][4];
    {
        const uint32_t* Qb = g_Qb + ((size_t)bt*128 + w*16) * 32;
        #pragma unroll
        for (int kt = 0; kt < 4; ++kt) {
            qa[kt][0] = Qb[(size_t)g*32     + 8*kt + t    ];
            qa[kt][1] = Qb[(size_t)(g+8)*32 + 8*kt + t    ];
            qa[kt][2] = Qb[(size_t)g*32     + 8*kt + t + 4];
            qa[kt][3] = Qb[(size_t)(g+8)*32 + 8*kt + t + 4];
        }
    }

    // ---- prologue: chunks 0,1 ----
    #pragma unroll
    for (int jc = 0; jc < 2; ++jc) {
        const uint32_t* Kg = g_Kb + (size_t)bt*4096 + jc*1024;
        const uint32_t* Vg = g_Vb + (size_t)bt*4096 + jc*1024;
        CPA16(sK + (uint32_t)(jc*1024 + tid*4)*4, Kg + tid*4);
        CPA16(sV + (uint32_t)(jc*1024 + tid*4)*4, Vg + tid*4);
        CPA_COMMIT();
    }

    float agg[8][4];
    #pragma unroll
    for (int nt = 0; nt < 8; ++nt)
        #pragma unroll
        for (int r = 0; r < 4; ++r) agg[nt][r] = 0.0f;
    float dsum0 = 0.0f, dsum1 = 0.0f;

    for (int ic = 0; ic < nchunks; ++ic) {
        CPA_WAIT1();
        __syncthreads();

        if (ic + 2 < nchunks) {
            const int jc = ic + 2;
            const int bufo = (jc % 3) * 1024;
            const uint32_t* Kg = g_Kb + (size_t)(bt - (jc>>2))*4096 + (jc&3)*1024;
            const uint32_t* Vg = g_Vb + (size_t)(bt - (jc>>2))*4096 + (jc&3)*1024;
            CPA16(sK + (uint32_t)(bufo + tid*4)*4, Kg + tid*4);
            CPA16(sV + (uint32_t)(bufo + tid*4)*4, Vg + tid*4);
        }
        CPA_COMMIT();

        const uint2* Kb = reinterpret_cast<const uint2*>(smu + (ic % 3) * 1024);
        const uint2* Vb = reinterpret_cast<const uint2*>(smu + 3072 + (ic % 3) * 1024);

        // ---- GEMM1: S(16x32) = Q * K^T, 16 bf16 MMAs ----
        float sc[4][4];
        #pragma unroll
        for (int nt = 0; nt < 4; ++nt)
            #pragma unroll
            for (int r = 0; r < 4; ++r) sc[nt][r] = 0.0f;

        #pragma unroll
        for (int kt = 0; kt < 4; ++kt) {
            #pragma unroll
            for (int nt = 0; nt < 4; ++nt) {
                uint2 b = Kb[(nt*4 + kt)*32 + lane];
                MMAB(sc[nt], qa[kt], b.x, b.y);
            }
        }

        // ---- exp2 (f32) + denominator partials (f32, pre-pack) ----
        #pragma unroll
        for (int nt = 0; nt < 4; ++nt) {
            float e0, e1, e2, e3;
            EX2(e0, sc[nt][0]); EX2(e1, sc[nt][1]);
            EX2(e2, sc[nt][2]); EX2(e3, sc[nt][3]);
            sc[nt][0] = e0; sc[nt][1] = e1; sc[nt][2] = e2; sc[nt][3] = e3;
            dsum0 += e0 + e1;
            dsum1 += e2 + e3;
        }

        // ---- GEMM2: agg += P * V, register-pure bf16 A-frags ----
        #pragma unroll
        for (int kk = 0; kk < 2; ++kk) {
            uint32_t pa[4];
            PKBF(pa[0], sc[2*kk  ][0], sc[2*kk  ][1]);
            PKBF(pa[1], sc[2*kk  ][2], sc[2*kk  ][3]);
            PKBF(pa[2], sc[2*kk+1][0], sc[2*kk+1][1]);
            PKBF(pa[3], sc[2*kk+1][2], sc[2*kk+1][3]);
            #pragma unroll
            for (int nt = 0; nt < 8; ++nt) {
                uint2 b = Vb[(kk*8 + nt)*32 + lane];
                MMAB(agg[nt], pa, b.x, b.y);
            }
        }
    }

    // ---- denominators ----
    const float padadd = (float)(LAGn - nvalid) * 128.0f;
    dsum0 += __shfl_xor_sync(0xffffffffu, dsum0, 1);
    dsum0 += __shfl_xor_sync(0xffffffffu, dsum0, 2);
    dsum1 += __shfl_xor_sync(0xffffffffu, dsum1, 1);
    dsum1 += __shfl_xor_sync(0xffffffffu, dsum1, 2);
    const float inv0 = 1.0f / (dsum0 + padadd);
    const float inv1 = 1.0f / (dsum1 + padadd);
    #pragma unroll
    for (int nt = 0; nt < 8; ++nt) {
        agg[nt][0] *= inv0; agg[nt][1] *= inv0;
        agg[nt][2] *= inv1; agg[nt][3] *= inv1;
    }

    // ---- load tf32 Wo (8192 floats = 32 KB) into smem ----
    CPA_WAIT0();
    __syncthreads();
    {
        const uint32_t sW = smem_u32(sm);
        #pragma unroll
        for (int q = 0; q < 8; ++q) {
            int idx = tid + q * 256;   // 0..2047 x 4 floats
            CPA16(sW + (uint32_t)idx*16, g_WoP + idx*4);
        }
        CPA_COMMIT();
        CPA_WAIT0();
    }
    __syncthreads();

    // ---- epilogue: out = relu([Q | agg] @ Wo + bo), tf32 MMAs ----
    // Q tf32 A-frags from natural g_Q
    uint32_t qt[8][4];
    {
        const float* Qn = g_Q + ((size_t)bt*128 + w*16) * 64;
        #pragma unroll
        for (int kt = 0; kt < 8; ++kt) {
            qt[kt][0] = __float_as_uint(Qn[(size_t)g    *64 + kt*8 + t    ]);
            qt[kt][1] = __float_as_uint(Qn[(size_t)(g+8)*64 + kt*8 + t    ]);
            qt[kt][2] = __float_as_uint(Qn[(size_t)g    *64 + kt*8 + t + 4]);
            qt[kt][3] = __float_as_uint(Qn[(size_t)(g+8)*64 + kt*8 + t + 4]);
        }
    }

    float ec[8][4];
    #pragma unroll
    for (int nt = 0; nt < 8; ++nt)
        #pragma unroll
        for (int r = 0; r < 4; ++r) ec[nt][r] = 0.0f;

    #pragma unroll
    for (int kt = 0; kt < 16; ++kt) {
        uint32_t a[4];
        if (kt < 8) {
            a[0] = qt[kt][0]; a[1] = qt[kt][1]; a[2] = qt[kt][2]; a[3] = qt[kt][3];
        } else {
            c2a(agg[kt-8], a, src0, src1, odd);
        }
        #pragma unroll
        for (int nt = 0; nt < 8; ++nt) {
            uint2 b = *reinterpret_cast<const uint2*>(&sm[((kt*8 + nt)*32 + lane)*2]);
            MMA(ec[nt], a, b.x, b.y);
        }
    }

    {
        const size_t rowA = (size_t)bt*128 + w*16 + g;
        #pragma unroll
        for (int nt = 0; nt < 8; ++nt) {
            int d0 = nt*8 + 2*t;
            float2 bv = *reinterpret_cast<const float2*>(&bo[d0]);
            float2 o0, o1;
            o0.x = fmaxf(ec[nt][0] + bv.x, 0.0f);
            o0.y = fmaxf(ec[nt][1] + bv.y, 0.0f);
            o1.x = fmaxf(ec[nt][2] + bv.x, 0.0f);
            o1.y = fmaxf(ec[nt][3] + bv.y, 0.0f);
            *reinterpret_cast<float2*>(&out[rowA*64 + d0])     = o0;
            *reinterpret_cast<float2*>(&out[(rowA+8)*64 + d0]) = o1;
        }
    }
}

// ---------------------------------------------------------------------------
extern "C" void kernel_launch(void* const* d_in, const int* in_sizes, int n_in,
                              void* d_out, int out_size)
{
    const float* X  = (const float*)d_in[0];
    const float* Wq = (const float*)d_in[1];
    const float* bq = (const float*)d_in[2];
    const float* Wk = (const float*)d_in[3];
    const float* bk = (const float*)d_in[4];
    const float* Wv = (const float*)d_in[5];
    const float* bv = (const float*)d_in[6];
    const float* Wo = (const float*)d_in[7];
    const float* bo = (const float*)d_in[8];
    float* out = (float*)d_out;

    cudaFuncSetAttribute(qkv_kernel,
                         cudaFuncAttributeMaxDynamicSharedMemorySize, QKV_SMEM);
    cudaFuncSetAttribute(attn_kernel,
                         cudaFuncAttributeMaxDynamicSharedMemorySize, SMEM_ATTN);

    qkv_kernel<<<Bdim*Tdim, 256, QKV_SMEM>>>(X, Wq, bq, Wk, bk, Wv, bv, Wo);
    attn_kernel<<<Bdim*Tdim, 256, SMEM_ATTN>>>(bo, out);
}